// round 4
// baseline (speedup 1.0000x reference)
#include <cuda_runtime.h>
#include <math.h>

#define NQ     4096
#define NKV    4096
#define DIMV   1024
#define NHEADS 16
#define HDIM   64

// Scratch (static device globals: allocation-free per harness rules)
__device__ float g_Qp[NQ * DIMV];
__device__ float g_Kp[NKV * DIMV];
__device__ float g_Vp[NKV * DIMV];
__device__ float g_Ao[NQ * DIMV];

// ---------------------------------------------------------------------------
// GEMM: C[M,N] = A[M,K] @ W[N,K]^T + bias[N]
// BM=128, BN=64, BK=16, 256 threads, 8x4 per-thread tile.
// Per k-step: 3 LDS.128 per 32 FFMA (48 B/FFMA-inst, under the 64 B/FFMA
// smem-crossbar ceiling at 2 FFMA-inst/cyc/SM) -> FFMA-bound, not LDS-bound.
// ---------------------------------------------------------------------------
__global__ void __launch_bounds__(256) gemm_bias_kernel(
    const float* __restrict__ A, const float* __restrict__ W,
    const float* __restrict__ bias, float* __restrict__ C,
    int M, int N, int K)
{
    __shared__ __align__(16) float As[16][132];  // [k][m]  128 + 4 pad
    __shared__ __align__(16) float Ws[16][68];   // [k][n]   64 + 4 pad

    const int m0  = blockIdx.y * 128;
    const int n0  = blockIdx.x * 64;
    const int tid = threadIdx.x;
    const int tx  = tid & 15;        // n sub-tile (4 cols)
    const int ty  = tid >> 4;        // m sub-tile (8 rows)
    const int lc  = tid & 15;        // loader: k column
    const int lr  = tid >> 4;        // loader: row (16 rows / pass)

    float acc[8][4];
#pragma unroll
    for (int i = 0; i < 8; i++)
#pragma unroll
        for (int j = 0; j < 4; j++) acc[i][j] = 0.f;

    for (int k0 = 0; k0 < K; k0 += 16) {
#pragma unroll
        for (int i = 0; i < 8; i++)
            As[lc][lr + 16 * i] = A[(size_t)(m0 + lr + 16 * i) * K + k0 + lc];
#pragma unroll
        for (int i = 0; i < 4; i++)
            Ws[lc][lr + 16 * i] = W[(size_t)(n0 + lr + 16 * i) * K + k0 + lc];
        __syncthreads();
#pragma unroll
        for (int k = 0; k < 16; k++) {
            float4 a4lo = *(const float4*)&As[k][ty * 8];
            float4 a4hi = *(const float4*)&As[k][ty * 8 + 4];
            float4 w4   = *(const float4*)&Ws[k][tx * 4];
            float a[8] = {a4lo.x, a4lo.y, a4lo.z, a4lo.w,
                          a4hi.x, a4hi.y, a4hi.z, a4hi.w};
            float w[4] = {w4.x, w4.y, w4.z, w4.w};
#pragma unroll
            for (int i = 0; i < 8; i++)
#pragma unroll
                for (int j = 0; j < 4; j++) acc[i][j] += a[i] * w[j];
        }
        __syncthreads();
    }

#pragma unroll
    for (int i = 0; i < 8; i++) {
#pragma unroll
        for (int j = 0; j < 4; j++) {
            C[(size_t)(m0 + ty * 8 + i) * N + n0 + tx * 4 + j] =
                acc[i][j] + bias[n0 + tx * 4 + j];
        }
    }
}

// ---------------------------------------------------------------------------
// Flash attention: block = (q-tile of 64 rows, head). Streams 64-row K/V
// tiles, online softmax, fp32 accumulators. Shared: Qs | KVs (K then V) | Ps.
// ---------------------------------------------------------------------------
#define ROWSTRIDE 68
#define ATTN_SMEM_FLOATS (3 * 64 * ROWSTRIDE + 3 * 64)

__global__ void __launch_bounds__(256) attn_kernel()
{
    extern __shared__ __align__(16) float sm[];
    float* Qs   = sm;                          // 64 x 68 (scaled Q)
    float* KVs  = sm + 64 * ROWSTRIDE;         // 64 x 68 (K tile, then V tile)
    float* Ps   = sm + 2 * 64 * ROWSTRIDE;     // 64 x 68 (scores -> probs)
    float* mrow = sm + 3 * 64 * ROWSTRIDE;     // 64
    float* lrow = mrow + 64;                   // 64
    float* crow = lrow + 64;                   // 64

    const int h   = blockIdx.y;
    const int q0  = blockIdx.x * 64;
    const int tid = threadIdx.x;
    const int tx  = tid & 15;
    const int ty  = tid >> 4;
    const float scale = 0.125f;   // 64^-0.5

    // Load Q tile (pre-scaled)
#pragma unroll
    for (int it = 0; it < 4; it++) {
        int lin = (tid + it * 256) * 4;
        int rr = lin >> 6, cc = lin & 63;
        float4 v = *(const float4*)&g_Qp[(size_t)(q0 + rr) * DIMV + h * HDIM + cc];
        v.x *= scale; v.y *= scale; v.z *= scale; v.w *= scale;
        *(float4*)&Qs[rr * ROWSTRIDE + cc] = v;
    }
    if (tid < 64) { mrow[tid] = -INFINITY; lrow[tid] = 0.f; }

    float acc[4][4];
#pragma unroll
    for (int i = 0; i < 4; i++)
#pragma unroll
        for (int j = 0; j < 4; j++) acc[i][j] = 0.f;

    __syncthreads();

    for (int j0 = 0; j0 < NKV; j0 += 64) {
        // ---- load K tile: KVs[kvrow][dim]
#pragma unroll
        for (int it = 0; it < 4; it++) {
            int lin = (tid + it * 256) * 4;
            int rr = lin >> 6, cc = lin & 63;
            *(float4*)&KVs[rr * ROWSTRIDE + cc] =
                *(const float4*)&g_Kp[(size_t)(j0 + rr) * DIMV + h * HDIM + cc];
        }
        __syncthreads();

        // ---- S = Qs @ K^T   (s[i][j]: q row ty*4+i, kv col tx*4+j)
        float s[4][4];
#pragma unroll
        for (int i = 0; i < 4; i++)
#pragma unroll
            for (int j = 0; j < 4; j++) s[i][j] = 0.f;

#pragma unroll 4
        for (int k = 0; k < 64; k += 4) {
            float4 a[4], w[4];
#pragma unroll
            for (int i = 0; i < 4; i++)
                a[i] = *(const float4*)&Qs[(ty * 4 + i) * ROWSTRIDE + k];
#pragma unroll
            for (int j = 0; j < 4; j++)
                w[j] = *(const float4*)&KVs[(tx * 4 + j) * ROWSTRIDE + k];
#pragma unroll
            for (int i = 0; i < 4; i++)
#pragma unroll
                for (int j = 0; j < 4; j++)
                    s[i][j] += a[i].x * w[j].x + a[i].y * w[j].y +
                               a[i].z * w[j].z + a[i].w * w[j].w;
        }
#pragma unroll
        for (int i = 0; i < 4; i++)
#pragma unroll
            for (int j = 0; j < 4; j++)
                Ps[(ty * 4 + i) * ROWSTRIDE + tx * 4 + j] = s[i][j];
        __syncthreads();

        // ---- online softmax: 4 threads per row, 16 cols each
        {
            int r  = tid >> 2;
            int qd = tid & 3;
            int cb = qd * 16;
            float mold = mrow[r];
            float mx = mold;
#pragma unroll
            for (int c = 0; c < 16; c++)
                mx = fmaxf(mx, Ps[r * ROWSTRIDE + cb + c]);
            mx = fmaxf(mx, __shfl_xor_sync(0xffffffffu, mx, 1));
            mx = fmaxf(mx, __shfl_xor_sync(0xffffffffu, mx, 2));
            float ssum = 0.f;
#pragma unroll
            for (int c = 0; c < 16; c++) {
                float p = __expf(Ps[r * ROWSTRIDE + cb + c] - mx);
                Ps[r * ROWSTRIDE + cb + c] = p;
                ssum += p;
            }
            ssum += __shfl_xor_sync(0xffffffffu, ssum, 1);
            ssum += __shfl_xor_sync(0xffffffffu, ssum, 2);
            if (qd == 0) {
                float corr = __expf(mold - mx);
                crow[r] = corr;
                lrow[r] = lrow[r] * corr + ssum;
                mrow[r] = mx;
            }
        }
        __syncthreads();

        // ---- rescale accumulators; load V tile (reuses KVs)
#pragma unroll
        for (int i = 0; i < 4; i++) {
            float cf = crow[ty * 4 + i];
#pragma unroll
            for (int j = 0; j < 4; j++) acc[i][j] *= cf;
        }
#pragma unroll
        for (int it = 0; it < 4; it++) {
            int lin = (tid + it * 256) * 4;
            int rr = lin >> 6, cc = lin & 63;
            *(float4*)&KVs[rr * ROWSTRIDE + cc] =
                *(const float4*)&g_Vp[(size_t)(j0 + rr) * DIMV + h * HDIM + cc];
        }
        __syncthreads();

        // ---- O += P @ V
#pragma unroll 4
        for (int k = 0; k < 64; k += 4) {
            float4 p4[4], v4[4];
#pragma unroll
            for (int i = 0; i < 4; i++)
                p4[i] = *(const float4*)&Ps[(ty * 4 + i) * ROWSTRIDE + k];
#pragma unroll
            for (int kk = 0; kk < 4; kk++)
                v4[kk] = *(const float4*)&KVs[(k + kk) * ROWSTRIDE + tx * 4];
#pragma unroll
            for (int i = 0; i < 4; i++) {
                acc[i][0] += p4[i].x * v4[0].x + p4[i].y * v4[1].x +
                             p4[i].z * v4[2].x + p4[i].w * v4[3].x;
                acc[i][1] += p4[i].x * v4[0].y + p4[i].y * v4[1].y +
                             p4[i].z * v4[2].y + p4[i].w * v4[3].y;
                acc[i][2] += p4[i].x * v4[0].z + p4[i].y * v4[1].z +
                             p4[i].z * v4[2].z + p4[i].w * v4[3].z;
                acc[i][3] += p4[i].x * v4[0].w + p4[i].y * v4[1].w +
                             p4[i].z * v4[2].w + p4[i].w * v4[3].w;
            }
        }
        __syncthreads();
    }

    // ---- normalize and write
#pragma unroll
    for (int i = 0; i < 4; i++) {
        float inv = 1.f / lrow[ty * 4 + i];
#pragma unroll
        for (int j = 0; j < 4; j++) {
            g_Ao[(size_t)(q0 + ty * 4 + i) * DIMV + h * HDIM + tx * 4 + j] =
                acc[i][j] * inv;
        }
    }
}

// ---------------------------------------------------------------------------
extern "C" void kernel_launch(void* const* d_in, const int* in_sizes, int n_in,
                              void* d_out, int out_size)
{
    const float* q   = (const float*)d_in[0];
    const float* kv  = (const float*)d_in[1];
    const float* q_w = (const float*)d_in[2];
    const float* q_b = (const float*)d_in[3];
    const float* k_w = (const float*)d_in[4];
    const float* k_b = (const float*)d_in[5];
    const float* v_w = (const float*)d_in[6];
    const float* v_b = (const float*)d_in[7];
    const float* o_w = (const float*)d_in[8];
    const float* o_b = (const float*)d_in[9];
    float* out = (float*)d_out;

    float *Qp, *Kp, *Vp, *Ao;
    cudaGetSymbolAddress((void**)&Qp, g_Qp);
    cudaGetSymbolAddress((void**)&Kp, g_Kp);
    cudaGetSymbolAddress((void**)&Vp, g_Vp);
    cudaGetSymbolAddress((void**)&Ao, g_Ao);

    const int attn_smem = ATTN_SMEM_FLOATS * (int)sizeof(float);  // ~53 KB
    cudaFuncSetAttribute(attn_kernel,
                         cudaFuncAttributeMaxDynamicSharedMemorySize, attn_smem);

    dim3 gg(DIMV / 64, NQ / 128);   // (16, 32)

    gemm_bias_kernel<<<gg, 256>>>(q,  q_w, q_b, Qp, NQ,  DIMV, DIMV);
    gemm_bias_kernel<<<gg, 256>>>(kv, k_w, k_b, Kp, NKV, DIMV, DIMV);
    gemm_bias_kernel<<<gg, 256>>>(kv, v_w, v_b, Vp, NKV, DIMV, DIMV);

    attn_kernel<<<dim3(NQ / 64, NHEADS), 256, attn_smem>>>();

    gemm_bias_kernel<<<gg, 256>>>(Ao, o_w, o_b, out, NQ, DIMV, DIMV);
}

// round 5
// speedup vs baseline: 1.4284x; 1.4284x over previous
#include <cuda_runtime.h>
#include <math.h>

#define NQ     4096
#define NKV    4096
#define DIMV   1024
#define NHEADS 16
#define HDIM   64

// Scratch (static device globals: allocation-free per harness rules)
__device__ float g_Qp[NQ * DIMV];
__device__ float g_Kp[NKV * DIMV];
__device__ float g_Vp[NKV * DIMV];
__device__ float g_Ao[NQ * DIMV];

// ---- packed fp32x2 helpers (sm_103a) --------------------------------------
#define FMA2(d, a, b) \
    asm("fma.rn.f32x2 %0, %1, %2, %0;" : "+l"(d) : "l"(a), "l"(b))
#define MUL2(d, a, b) \
    asm("mul.rn.f32x2 %0, %1, %2;" : "=l"(d) : "l"(a), "l"(b))
#define DUP2(d, s) \
    asm("mov.b64 %0, {%1, %1};" : "=l"(d) : "r"(__float_as_uint(s)))
#define UNPK2(lo, hi, s) \
    asm("mov.b64 {%0, %1}, %2;" : "=f"(lo), "=f"(hi) : "l"(s))

// ---------------------------------------------------------------------------
// GEMM: C[M,N] = A[M,K] @ W[N,K]^T + bias[N]
// BM=128, BN=64, BK=16, 256 threads, 8x4 per-thread tile.
// ---------------------------------------------------------------------------
__global__ void __launch_bounds__(256) gemm_bias_kernel(
    const float* __restrict__ A, const float* __restrict__ W,
    const float* __restrict__ bias, float* __restrict__ C,
    int M, int N, int K)
{
    __shared__ __align__(16) float As[16][132];  // [k][m]  128 + 4 pad
    __shared__ __align__(16) float Ws[16][68];   // [k][n]   64 + 4 pad

    const int m0  = blockIdx.y * 128;
    const int n0  = blockIdx.x * 64;
    const int tid = threadIdx.x;
    const int tx  = tid & 15;        // n sub-tile (4 cols)
    const int ty  = tid >> 4;        // m sub-tile (8 rows)
    const int lc  = tid & 15;        // loader: k column
    const int lr  = tid >> 4;        // loader: row (16 rows / pass)

    float acc[8][4];
#pragma unroll
    for (int i = 0; i < 8; i++)
#pragma unroll
        for (int j = 0; j < 4; j++) acc[i][j] = 0.f;

    for (int k0 = 0; k0 < K; k0 += 16) {
#pragma unroll
        for (int i = 0; i < 8; i++)
            As[lc][lr + 16 * i] = A[(size_t)(m0 + lr + 16 * i) * K + k0 + lc];
#pragma unroll
        for (int i = 0; i < 4; i++)
            Ws[lc][lr + 16 * i] = W[(size_t)(n0 + lr + 16 * i) * K + k0 + lc];
        __syncthreads();
#pragma unroll
        for (int k = 0; k < 16; k++) {
            float4 a4lo = *(const float4*)&As[k][ty * 8];
            float4 a4hi = *(const float4*)&As[k][ty * 8 + 4];
            float4 w4   = *(const float4*)&Ws[k][tx * 4];
            float a[8] = {a4lo.x, a4lo.y, a4lo.z, a4lo.w,
                          a4hi.x, a4hi.y, a4hi.z, a4hi.w};
            float w[4] = {w4.x, w4.y, w4.z, w4.w};
#pragma unroll
            for (int i = 0; i < 8; i++)
#pragma unroll
                for (int j = 0; j < 4; j++) acc[i][j] += a[i] * w[j];
        }
        __syncthreads();
    }

#pragma unroll
    for (int i = 0; i < 8; i++) {
#pragma unroll
        for (int j = 0; j < 4; j++) {
            C[(size_t)(m0 + ty * 8 + i) * N + n0 + tx * 4 + j] =
                acc[i][j] + bias[n0 + tx * 4 + j];
        }
    }
}

// ---------------------------------------------------------------------------
// Flash attention v2: block = 128 q rows x head, 256 threads, 8x4 thread tile.
//   Qs [128][68] row-major (broadcast reads, conflict-free)
//   Kt [64][68]  dim-major (TRANSPOSED: w-reads consecutive -> no conflicts)
//   Vs [64][68]  row-major (already conflict-free)
//   Ps [128][68] probabilities (softmax itself is register-resident)
// Inner products in packed f32x2 (2 fp32 FMA lanes / inst).
// ---------------------------------------------------------------------------
#define RS 68
#define ATTN_SMEM_FLOATS ((128 + 64 + 64 + 128) * RS)

__global__ void __launch_bounds__(256, 2) attn_kernel()
{
    extern __shared__ __align__(16) float sm[];
    float* Qs = sm;                    // 128 x 68
    float* Kt = sm + 128 * RS;         //  64 x 68 (transposed)
    float* Vs = Kt + 64 * RS;          //  64 x 68
    float* Ps = Vs + 64 * RS;          // 128 x 68

    const int h   = blockIdx.y;
    const int q0  = blockIdx.x * 128;
    const int tid = threadIdx.x;
    const int tx  = tid & 15;          // 4 kv-cols / dims
    const int ty  = tid >> 4;          // 8 q-rows
    // fold softmax scale and log2(e) into Q so we can use exp2f
    const float qscale = 0.125f * 1.44269504088896340736f;

    // ---- load Q tile (scaled): 128x64 floats, 8 float4 per thread
#pragma unroll
    for (int it = 0; it < 8; it++) {
        int lin = (tid + it * 256) * 4;
        int rr = lin >> 6, cc = lin & 63;
        float4 v = *(const float4*)&g_Qp[(size_t)(q0 + rr) * DIMV + h * HDIM + cc];
        v.x *= qscale; v.y *= qscale; v.z *= qscale; v.w *= qscale;
        *(float4*)&Qs[rr * RS + cc] = v;
    }

    unsigned long long acc2[8][2];
    float mrow[8], lrow[8];
#pragma unroll
    for (int i = 0; i < 8; i++) {
        acc2[i][0] = 0ULL; acc2[i][1] = 0ULL;
        mrow[i] = -INFINITY; lrow[i] = 0.f;
    }

    for (int j0 = 0; j0 < NKV; j0 += 64) {
        __syncthreads();   // prev PV done: Kt/Vs/Ps free to rewrite

        // ---- load K tile TRANSPOSED: Kt[dim][kvrow]
#pragma unroll
        for (int it = 0; it < 4; it++) {
            int lin = (tid + it * 256) * 4;
            int rr = lin >> 6, cc = lin & 63;
            float4 v = *(const float4*)&g_Kp[(size_t)(j0 + rr) * DIMV + h * HDIM + cc];
            Kt[(cc + 0) * RS + rr] = v.x;
            Kt[(cc + 1) * RS + rr] = v.y;
            Kt[(cc + 2) * RS + rr] = v.z;
            Kt[(cc + 3) * RS + rr] = v.w;
        }
        // ---- load V tile natural: Vs[kvrow][dim]
#pragma unroll
        for (int it = 0; it < 4; it++) {
            int lin = (tid + it * 256) * 4;
            int rr = lin >> 6, cc = lin & 63;
            *(float4*)&Vs[rr * RS + cc] =
                *(const float4*)&g_Vp[(size_t)(j0 + rr) * DIMV + h * HDIM + cc];
        }
        __syncthreads();   // tiles ready (also orders Qs stores on iter 0)

        // ---- S = Q K^T : s2[i][jp] packs kv-cols (4tx+2jp, 4tx+2jp+1)
        unsigned long long s2[8][2];
#pragma unroll
        for (int i = 0; i < 8; i++) { s2[i][0] = 0ULL; s2[i][1] = 0ULL; }

#pragma unroll 2
        for (int k = 0; k < 64; k += 4) {
            ulonglong2 w[4];
#pragma unroll
            for (int u = 0; u < 4; u++)
                w[u] = *(const ulonglong2*)&Kt[(k + u) * RS + tx * 4];
#pragma unroll
            for (int i = 0; i < 8; i++) {
                float4 aq = *(const float4*)&Qs[(ty * 8 + i) * RS + k];
                unsigned long long a2;
                DUP2(a2, aq.x); FMA2(s2[i][0], a2, w[0].x); FMA2(s2[i][1], a2, w[0].y);
                DUP2(a2, aq.y); FMA2(s2[i][0], a2, w[1].x); FMA2(s2[i][1], a2, w[1].y);
                DUP2(a2, aq.z); FMA2(s2[i][0], a2, w[2].x); FMA2(s2[i][1], a2, w[2].y);
                DUP2(a2, aq.w); FMA2(s2[i][0], a2, w[3].x); FMA2(s2[i][1], a2, w[3].y);
            }
        }

        // ---- register softmax (16-lane row groups via shfl_xor)
#pragma unroll
        for (int i = 0; i < 8; i++) {
            float s0, s1, s2f, s3;
            UNPK2(s0, s1, s2[i][0]);
            UNPK2(s2f, s3, s2[i][1]);
            float mx = fmaxf(fmaxf(s0, s1), fmaxf(s2f, s3));
            mx = fmaxf(mx, mrow[i]);
            mx = fmaxf(mx, __shfl_xor_sync(0xffffffffu, mx, 1));
            mx = fmaxf(mx, __shfl_xor_sync(0xffffffffu, mx, 2));
            mx = fmaxf(mx, __shfl_xor_sync(0xffffffffu, mx, 4));
            mx = fmaxf(mx, __shfl_xor_sync(0xffffffffu, mx, 8));
            float p0 = exp2f(s0 - mx), p1 = exp2f(s1 - mx);
            float p2 = exp2f(s2f - mx), p3 = exp2f(s3 - mx);
            float ssum = (p0 + p1) + (p2 + p3);
            ssum += __shfl_xor_sync(0xffffffffu, ssum, 1);
            ssum += __shfl_xor_sync(0xffffffffu, ssum, 2);
            ssum += __shfl_xor_sync(0xffffffffu, ssum, 4);
            ssum += __shfl_xor_sync(0xffffffffu, ssum, 8);
            float corr = exp2f(mrow[i] - mx);
            mrow[i] = mx;
            lrow[i] = lrow[i] * corr + ssum;
            unsigned long long c2;
            DUP2(c2, corr);
            MUL2(acc2[i][0], acc2[i][0], c2);
            MUL2(acc2[i][1], acc2[i][1], c2);
            float4 pv = make_float4(p0, p1, p2, p3);
            *(float4*)&Ps[(ty * 8 + i) * RS + tx * 4] = pv;
        }
        __syncthreads();   // Ps complete

        // ---- O += P @ V : acc2[i][dp] packs dims (4tx+2dp, 4tx+2dp+1)
#pragma unroll 2
        for (int k = 0; k < 64; k += 4) {
            ulonglong2 v[4];
#pragma unroll
            for (int u = 0; u < 4; u++)
                v[u] = *(const ulonglong2*)&Vs[(k + u) * RS + tx * 4];
#pragma unroll
            for (int i = 0; i < 8; i++) {
                float4 pq = *(const float4*)&Ps[(ty * 8 + i) * RS + k];
                unsigned long long p2;
                DUP2(p2, pq.x); FMA2(acc2[i][0], p2, v[0].x); FMA2(acc2[i][1], p2, v[0].y);
                DUP2(p2, pq.y); FMA2(acc2[i][0], p2, v[1].x); FMA2(acc2[i][1], p2, v[1].y);
                DUP2(p2, pq.z); FMA2(acc2[i][0], p2, v[2].x); FMA2(acc2[i][1], p2, v[2].y);
                DUP2(p2, pq.w); FMA2(acc2[i][0], p2, v[3].x); FMA2(acc2[i][1], p2, v[3].y);
            }
        }
    }

    // ---- normalize and write
#pragma unroll
    for (int i = 0; i < 8; i++) {
        float inv = 1.f / lrow[i];
        float o0, o1, o2, o3;
        UNPK2(o0, o1, acc2[i][0]);
        UNPK2(o2, o3, acc2[i][1]);
        float4 ov = make_float4(o0 * inv, o1 * inv, o2 * inv, o3 * inv);
        *(float4*)&g_Ao[(size_t)(q0 + ty * 8 + i) * DIMV + h * HDIM + tx * 4] = ov;
    }
}

// ---------------------------------------------------------------------------
extern "C" void kernel_launch(void* const* d_in, const int* in_sizes, int n_in,
                              void* d_out, int out_size)
{
    const float* q   = (const float*)d_in[0];
    const float* kv  = (const float*)d_in[1];
    const float* q_w = (const float*)d_in[2];
    const float* q_b = (const float*)d_in[3];
    const float* k_w = (const float*)d_in[4];
    const float* k_b = (const float*)d_in[5];
    const float* v_w = (const float*)d_in[6];
    const float* v_b = (const float*)d_in[7];
    const float* o_w = (const float*)d_in[8];
    const float* o_b = (const float*)d_in[9];
    float* out = (float*)d_out;

    float *Qp, *Kp, *Vp, *Ao;
    cudaGetSymbolAddress((void**)&Qp, g_Qp);
    cudaGetSymbolAddress((void**)&Kp, g_Kp);
    cudaGetSymbolAddress((void**)&Vp, g_Vp);
    cudaGetSymbolAddress((void**)&Ao, g_Ao);

    const int attn_smem = ATTN_SMEM_FLOATS * (int)sizeof(float);  // 104448 B
    cudaFuncSetAttribute(attn_kernel,
                         cudaFuncAttributeMaxDynamicSharedMemorySize, attn_smem);

    dim3 gg(DIMV / 64, NQ / 128);   // (16, 32)

    gemm_bias_kernel<<<gg, 256>>>(q,  q_w, q_b, Qp, NQ,  DIMV, DIMV);
    gemm_bias_kernel<<<gg, 256>>>(kv, k_w, k_b, Kp, NKV, DIMV, DIMV);
    gemm_bias_kernel<<<gg, 256>>>(kv, v_w, v_b, Vp, NKV, DIMV, DIMV);

    attn_kernel<<<dim3(NQ / 128, NHEADS), 256, attn_smem>>>();

    gemm_bias_kernel<<<gg, 256>>>(Ao, o_w, o_b, out, NQ, DIMV, DIMV);
}

// round 12
// speedup vs baseline: 1.9155x; 1.3410x over previous
#include <cuda_runtime.h>
#include <cstdint>
#include <math.h>

#define NQ     4096
#define NKV    4096
#define DIMV   1024
#define NHEADS 16
#define HDIM   64

// Scratch (static device globals: allocation-free per harness rules)
__device__ float g_Qp[NQ * DIMV];
__device__ float g_Kp[NKV * DIMV];
__device__ float g_Vp[NKV * DIMV];
__device__ float g_Ao[NQ * DIMV];

// ---- packed fp32x2 helpers (sm_103a) --------------------------------------
#define FMA2(d, a, b) \
    asm("fma.rn.f32x2 %0, %1, %2, %0;" : "+l"(d) : "l"(a), "l"(b))
#define MUL2(d, a, b) \
    asm("mul.rn.f32x2 %0, %1, %2;" : "=l"(d) : "l"(a), "l"(b))
#define DUP2(d, s) \
    asm("mov.b64 %0, {%1, %1};" : "=l"(d) : "r"(__float_as_uint(s)))
#define UNPK2(lo, hi, s) \
    asm("mov.b64 {%0, %1}, %2;" : "=f"(lo), "=f"(hi) : "l"(s))

// ---- tf32 mma.sync helpers (arch-portable: sm_80+ PTX, works on sm_103) ----
#define CVT_TF32(u, f) asm("cvt.rna.tf32.f32 %0, %1;" : "=r"(u) : "f"(f))

__device__ __forceinline__ void mma_tf32(float* d, const uint32_t* a,
                                         const uint32_t* b)
{
    asm volatile(
        "mma.sync.aligned.m16n8k8.row.col.f32.tf32.tf32.f32 "
        "{%0,%1,%2,%3}, {%4,%5,%6,%7}, {%8,%9}, {%0,%1,%2,%3};"
        : "+f"(d[0]), "+f"(d[1]), "+f"(d[2]), "+f"(d[3])
        : "r"(a[0]), "r"(a[1]), "r"(a[2]), "r"(a[3]),
          "r"(b[0]), "r"(b[1]));
}

// ---------------------------------------------------------------------------
// tf32 tensor-core GEMM: C[M,1024] = A[M,1024] @ W[1024,1024]^T + bias.
// CTA tile 128x128, BK=32, 8 warps in 2(m)x4(n) grid, m16n8k8 tf32 mma.
// SMEM stride 36 floats -> all fragment LDS are bank-conflict-free
// (bank = (4*row + col) mod 32, distinct across the warp).
// ---------------------------------------------------------------------------
#define GK 1024
#define GN 1024
#define GST 36

__global__ void __launch_bounds__(256, 2) gemm_tf32_kernel(
    const float* __restrict__ A, const float* __restrict__ W,
    const float* __restrict__ bias, float* __restrict__ C)
{
    __shared__ __align__(16) float As[128][GST];
    __shared__ __align__(16) float Bs[128][GST];

    const int tid = threadIdx.x;
    const int wid = tid >> 5;
    const int lid = tid & 31;
    const int m0  = blockIdx.y * 128;
    const int n0  = blockIdx.x * 128;
    const int wm  = (wid & 1) * 64;    // warp m-offset within CTA
    const int wn  = (wid >> 1) * 32;   // warp n-offset within CTA
    const int r   = lid >> 2;          // 0..7
    const int c   = lid & 3;           // 0..3

    float d[16][4];
#pragma unroll
    for (int i = 0; i < 16; i++)
#pragma unroll
        for (int j = 0; j < 4; j++) d[i][j] = 0.f;

    for (int kb = 0; kb < GK; kb += 32) {
        __syncthreads();   // previous compute done before overwriting tiles
        // ---- load 128x32 A-tile and W-tile, fp32 -> tf32 (rna)
#pragma unroll
        for (int t = 0; t < 4; t++) {
            int idx = tid + 256 * t;
            int row = idx >> 3, c4 = (idx & 7) * 4;
            float4 va = *(const float4*)&A[(size_t)(m0 + row) * GK + kb + c4];
            float4 vb = *(const float4*)&W[(size_t)(n0 + row) * GK + kb + c4];
            uint32_t u;
            CVT_TF32(u, va.x); As[row][c4 + 0] = __uint_as_float(u);
            CVT_TF32(u, va.y); As[row][c4 + 1] = __uint_as_float(u);
            CVT_TF32(u, va.z); As[row][c4 + 2] = __uint_as_float(u);
            CVT_TF32(u, va.w); As[row][c4 + 3] = __uint_as_float(u);
            CVT_TF32(u, vb.x); Bs[row][c4 + 0] = __uint_as_float(u);
            CVT_TF32(u, vb.y); Bs[row][c4 + 1] = __uint_as_float(u);
            CVT_TF32(u, vb.z); Bs[row][c4 + 2] = __uint_as_float(u);
            CVT_TF32(u, vb.w); Bs[row][c4 + 3] = __uint_as_float(u);
        }
        __syncthreads();

        // ---- 4 k-steps of 8, 16 mma each
#pragma unroll
        for (int ks = 0; ks < 4; ks++) {
            const int kk = ks * 8;
            uint32_t af[4][4], bf[4][2];
#pragma unroll
            for (int i = 0; i < 4; i++) {
                const int mrow = wm + 16 * i + r;
                af[i][0] = __float_as_uint(As[mrow    ][kk + c    ]);
                af[i][1] = __float_as_uint(As[mrow + 8][kk + c    ]);
                af[i][2] = __float_as_uint(As[mrow    ][kk + c + 4]);
                af[i][3] = __float_as_uint(As[mrow + 8][kk + c + 4]);
            }
#pragma unroll
            for (int j = 0; j < 4; j++) {
                const int nrow = wn + 8 * j + r;
                bf[j][0] = __float_as_uint(Bs[nrow][kk + c    ]);
                bf[j][1] = __float_as_uint(Bs[nrow][kk + c + 4]);
            }
#pragma unroll
            for (int i = 0; i < 4; i++)
#pragma unroll
                for (int j = 0; j < 4; j++)
                    mma_tf32(d[i * 4 + j], af[i], bf[j]);
        }
    }

    // ---- epilogue: D + bias -> C  (d0,d1 at (row,col..col+1); d2,d3 at row+8)
#pragma unroll
    for (int i = 0; i < 4; i++) {
#pragma unroll
        for (int j = 0; j < 4; j++) {
            const int row0 = m0 + wm + 16 * i + r;
            const int col0 = n0 + wn + 8 * j + 2 * c;
            float2 bv = *(const float2*)&bias[col0];
            float2 lo = make_float2(d[i * 4 + j][0] + bv.x,
                                    d[i * 4 + j][1] + bv.y);
            float2 hi = make_float2(d[i * 4 + j][2] + bv.x,
                                    d[i * 4 + j][3] + bv.y);
            *(float2*)&C[(size_t)row0 * GN + col0]       = lo;
            *(float2*)&C[(size_t)(row0 + 8) * GN + col0] = hi;
        }
    }
}

// ---------------------------------------------------------------------------
// Flash attention (proven R5 version, unchanged): 128 q rows x head,
// 256 threads, transposed K tile, register softmax, packed f32x2 math.
// ---------------------------------------------------------------------------
#define RS 68
#define ATTN_SMEM_FLOATS ((128 + 64 + 64 + 128) * RS)

__global__ void __launch_bounds__(256, 2) attn_kernel()
{
    extern __shared__ __align__(16) float sm[];
    float* Qs = sm;                    // 128 x 68
    float* Kt = sm + 128 * RS;         //  64 x 68 (transposed)
    float* Vs = Kt + 64 * RS;          //  64 x 68
    float* Ps = Vs + 64 * RS;          // 128 x 68

    const int h   = blockIdx.y;
    const int q0  = blockIdx.x * 128;
    const int tid = threadIdx.x;
    const int tx  = tid & 15;          // 4 kv-cols / dims
    const int ty  = tid >> 4;          // 8 q-rows
    const float qscale = 0.125f * 1.44269504088896340736f;

#pragma unroll
    for (int it = 0; it < 8; it++) {
        int lin = (tid + it * 256) * 4;
        int rr = lin >> 6, cc = lin & 63;
        float4 v = *(const float4*)&g_Qp[(size_t)(q0 + rr) * DIMV + h * HDIM + cc];
        v.x *= qscale; v.y *= qscale; v.z *= qscale; v.w *= qscale;
        *(float4*)&Qs[rr * RS + cc] = v;
    }

    unsigned long long acc2[8][2];
    float mrow[8], lrow[8];
#pragma unroll
    for (int i = 0; i < 8; i++) {
        acc2[i][0] = 0ULL; acc2[i][1] = 0ULL;
        mrow[i] = -INFINITY; lrow[i] = 0.f;
    }

    for (int j0 = 0; j0 < NKV; j0 += 64) {
        __syncthreads();

#pragma unroll
        for (int it = 0; it < 4; it++) {
            int lin = (tid + it * 256) * 4;
            int rr = lin >> 6, cc = lin & 63;
            float4 v = *(const float4*)&g_Kp[(size_t)(j0 + rr) * DIMV + h * HDIM + cc];
            Kt[(cc + 0) * RS + rr] = v.x;
            Kt[(cc + 1) * RS + rr] = v.y;
            Kt[(cc + 2) * RS + rr] = v.z;
            Kt[(cc + 3) * RS + rr] = v.w;
        }
#pragma unroll
        for (int it = 0; it < 4; it++) {
            int lin = (tid + it * 256) * 4;
            int rr = lin >> 6, cc = lin & 63;
            *(float4*)&Vs[rr * RS + cc] =
                *(const float4*)&g_Vp[(size_t)(j0 + rr) * DIMV + h * HDIM + cc];
        }
        __syncthreads();

        unsigned long long s2[8][2];
#pragma unroll
        for (int i = 0; i < 8; i++) { s2[i][0] = 0ULL; s2[i][1] = 0ULL; }

#pragma unroll 2
        for (int k = 0; k < 64; k += 4) {
            ulonglong2 w[4];
#pragma unroll
            for (int u = 0; u < 4; u++)
                w[u] = *(const ulonglong2*)&Kt[(k + u) * RS + tx * 4];
#pragma unroll
            for (int i = 0; i < 8; i++) {
                float4 aq = *(const float4*)&Qs[(ty * 8 + i) * RS + k];
                unsigned long long a2;
                DUP2(a2, aq.x); FMA2(s2[i][0], a2, w[0].x); FMA2(s2[i][1], a2, w[0].y);
                DUP2(a2, aq.y); FMA2(s2[i][0], a2, w[1].x); FMA2(s2[i][1], a2, w[1].y);
                DUP2(a2, aq.z); FMA2(s2[i][0], a2, w[2].x); FMA2(s2[i][1], a2, w[2].y);
                DUP2(a2, aq.w); FMA2(s2[i][0], a2, w[3].x); FMA2(s2[i][1], a2, w[3].y);
            }
        }

#pragma unroll
        for (int i = 0; i < 8; i++) {
            float s0, s1, s2f, s3;
            UNPK2(s0, s1, s2[i][0]);
            UNPK2(s2f, s3, s2[i][1]);
            float mx = fmaxf(fmaxf(s0, s1), fmaxf(s2f, s3));
            mx = fmaxf(mx, mrow[i]);
            mx = fmaxf(mx, __shfl_xor_sync(0xffffffffu, mx, 1));
            mx = fmaxf(mx, __shfl_xor_sync(0xffffffffu, mx, 2));
            mx = fmaxf(mx, __shfl_xor_sync(0xffffffffu, mx, 4));
            mx = fmaxf(mx, __shfl_xor_sync(0xffffffffu, mx, 8));
            float p0 = exp2f(s0 - mx), p1 = exp2f(s1 - mx);
            float p2 = exp2f(s2f - mx), p3 = exp2f(s3 - mx);
            float ssum = (p0 + p1) + (p2 + p3);
            ssum += __shfl_xor_sync(0xffffffffu, ssum, 1);
            ssum += __shfl_xor_sync(0xffffffffu, ssum, 2);
            ssum += __shfl_xor_sync(0xffffffffu, ssum, 4);
            ssum += __shfl_xor_sync(0xffffffffu, ssum, 8);
            float corr = exp2f(mrow[i] - mx);
            mrow[i] = mx;
            lrow[i] = lrow[i] * corr + ssum;
            unsigned long long c2;
            DUP2(c2, corr);
            MUL2(acc2[i][0], acc2[i][0], c2);
            MUL2(acc2[i][1], acc2[i][1], c2);
            float4 pv = make_float4(p0, p1, p2, p3);
            *(float4*)&Ps[(ty * 8 + i) * RS + tx * 4] = pv;
        }
        __syncthreads();

#pragma unroll 2
        for (int k = 0; k < 64; k += 4) {
            ulonglong2 v[4];
#pragma unroll
            for (int u = 0; u < 4; u++)
                v[u] = *(const ulonglong2*)&Vs[(k + u) * RS + tx * 4];
#pragma unroll
            for (int i = 0; i < 8; i++) {
                float4 pq = *(const float4*)&Ps[(ty * 8 + i) * RS + k];
                unsigned long long p2;
                DUP2(p2, pq.x); FMA2(acc2[i][0], p2, v[0].x); FMA2(acc2[i][1], p2, v[0].y);
                DUP2(p2, pq.y); FMA2(acc2[i][0], p2, v[1].x); FMA2(acc2[i][1], p2, v[1].y);
                DUP2(p2, pq.z); FMA2(acc2[i][0], p2, v[2].x); FMA2(acc2[i][1], p2, v[2].y);
                DUP2(p2, pq.w); FMA2(acc2[i][0], p2, v[3].x); FMA2(acc2[i][1], p2, v[3].y);
            }
        }
    }

#pragma unroll
    for (int i = 0; i < 8; i++) {
        float inv = 1.f / lrow[i];
        float o0, o1, o2, o3;
        UNPK2(o0, o1, acc2[i][0]);
        UNPK2(o2, o3, acc2[i][1]);
        float4 ov = make_float4(o0 * inv, o1 * inv, o2 * inv, o3 * inv);
        *(float4*)&g_Ao[(size_t)(q0 + ty * 8 + i) * DIMV + h * HDIM + tx * 4] = ov;
    }
}

// ---------------------------------------------------------------------------
extern "C" void kernel_launch(void* const* d_in, const int* in_sizes, int n_in,
                              void* d_out, int out_size)
{
    const float* q   = (const float*)d_in[0];
    const float* kv  = (const float*)d_in[1];
    const float* q_w = (const float*)d_in[2];
    const float* q_b = (const float*)d_in[3];
    const float* k_w = (const float*)d_in[4];
    const float* k_b = (const float*)d_in[5];
    const float* v_w = (const float*)d_in[6];
    const float* v_b = (const float*)d_in[7];
    const float* o_w = (const float*)d_in[8];
    const float* o_b = (const float*)d_in[9];
    float* out = (float*)d_out;

    float *Qp, *Kp, *Vp, *Ao;
    cudaGetSymbolAddress((void**)&Qp, g_Qp);
    cudaGetSymbolAddress((void**)&Kp, g_Kp);
    cudaGetSymbolAddress((void**)&Vp, g_Vp);
    cudaGetSymbolAddress((void**)&Ao, g_Ao);

    const int attn_smem = ATTN_SMEM_FLOATS * (int)sizeof(float);  // 104448 B
    cudaFuncSetAttribute(attn_kernel,
                         cudaFuncAttributeMaxDynamicSharedMemorySize, attn_smem);

    dim3 gg(GN / 128, NQ / 128);   // (8, 32)

    gemm_tf32_kernel<<<gg, 256>>>(q,  q_w, q_b, Qp);
    gemm_tf32_kernel<<<gg, 256>>>(kv, k_w, k_b, Kp);
    gemm_tf32_kernel<<<gg, 256>>>(kv, v_w, v_b, Vp);

    attn_kernel<<<dim3(NQ / 128, NHEADS), 256, attn_smem>>>();

    gemm_tf32_kernel<<<gg, 256>>>(Ao, o_w, o_b, out);
}

// round 17
// speedup vs baseline: 2.9111x; 1.5198x over previous
#include <cuda_runtime.h>
#include <cstdint>
#include <math.h>

#define NQ     4096
#define NKV    4096
#define DIMV   1024
#define NHEADS 16
#define HDIM   64

// Scratch (static device globals: allocation-free per harness rules)
__device__ float g_Qp[NQ * DIMV];
__device__ float g_Kp[NKV * DIMV];
__device__ float g_Vp[NKV * DIMV];
__device__ float g_Ao[NQ * DIMV];

// ---- tf32 mma.sync helpers (arch-portable: sm_80+ PTX, works on sm_103) ----
#define CVT_TF32(u, f) asm("cvt.rna.tf32.f32 %0, %1;" : "=r"(u) : "f"(f))

__device__ __forceinline__ void mma_tf32(float* d, const uint32_t* a,
                                         const uint32_t* b)
{
    asm volatile(
        "mma.sync.aligned.m16n8k8.row.col.f32.tf32.tf32.f32 "
        "{%0,%1,%2,%3}, {%4,%5,%6,%7}, {%8,%9}, {%0,%1,%2,%3};"
        : "+f"(d[0]), "+f"(d[1]), "+f"(d[2]), "+f"(d[3])
        : "r"(a[0]), "r"(a[1]), "r"(a[2]), "r"(a[3]),
          "r"(b[0]), "r"(b[1]));
}

// ---------------------------------------------------------------------------
// tf32 tensor-core GEMM (proven R12): C = A @ W^T + bias, CTA 128x128, BK=32.
// ---------------------------------------------------------------------------
#define GK 1024
#define GN 1024
#define GST 36

__global__ void __launch_bounds__(256, 2) gemm_tf32_kernel(
    const float* __restrict__ A, const float* __restrict__ W,
    const float* __restrict__ bias, float* __restrict__ C)
{
    __shared__ __align__(16) float As[128][GST];
    __shared__ __align__(16) float Bs[128][GST];

    const int tid = threadIdx.x;
    const int wid = tid >> 5;
    const int lid = tid & 31;
    const int m0  = blockIdx.y * 128;
    const int n0  = blockIdx.x * 128;
    const int wm  = (wid & 1) * 64;
    const int wn  = (wid >> 1) * 32;
    const int r   = lid >> 2;
    const int c   = lid & 3;

    float d[16][4];
#pragma unroll
    for (int i = 0; i < 16; i++)
#pragma unroll
        for (int j = 0; j < 4; j++) d[i][j] = 0.f;

    for (int kb = 0; kb < GK; kb += 32) {
        __syncthreads();
#pragma unroll
        for (int t = 0; t < 4; t++) {
            int idx = tid + 256 * t;
            int row = idx >> 3, c4 = (idx & 7) * 4;
            float4 va = *(const float4*)&A[(size_t)(m0 + row) * GK + kb + c4];
            float4 vb = *(const float4*)&W[(size_t)(n0 + row) * GK + kb + c4];
            uint32_t u;
            CVT_TF32(u, va.x); As[row][c4 + 0] = __uint_as_float(u);
            CVT_TF32(u, va.y); As[row][c4 + 1] = __uint_as_float(u);
            CVT_TF32(u, va.z); As[row][c4 + 2] = __uint_as_float(u);
            CVT_TF32(u, va.w); As[row][c4 + 3] = __uint_as_float(u);
            CVT_TF32(u, vb.x); Bs[row][c4 + 0] = __uint_as_float(u);
            CVT_TF32(u, vb.y); Bs[row][c4 + 1] = __uint_as_float(u);
            CVT_TF32(u, vb.z); Bs[row][c4 + 2] = __uint_as_float(u);
            CVT_TF32(u, vb.w); Bs[row][c4 + 3] = __uint_as_float(u);
        }
        __syncthreads();

#pragma unroll
        for (int ks = 0; ks < 4; ks++) {
            const int kk = ks * 8;
            uint32_t af[4][4], bf[4][2];
#pragma unroll
            for (int i = 0; i < 4; i++) {
                const int mrow = wm + 16 * i + r;
                af[i][0] = __float_as_uint(As[mrow    ][kk + c    ]);
                af[i][1] = __float_as_uint(As[mrow + 8][kk + c    ]);
                af[i][2] = __float_as_uint(As[mrow    ][kk + c + 4]);
                af[i][3] = __float_as_uint(As[mrow + 8][kk + c + 4]);
            }
#pragma unroll
            for (int j = 0; j < 4; j++) {
                const int nrow = wn + 8 * j + r;
                bf[j][0] = __float_as_uint(Bs[nrow][kk + c    ]);
                bf[j][1] = __float_as_uint(Bs[nrow][kk + c + 4]);
            }
#pragma unroll
            for (int i = 0; i < 4; i++)
#pragma unroll
                for (int j = 0; j < 4; j++)
                    mma_tf32(d[i * 4 + j], af[i], bf[j]);
        }
    }

#pragma unroll
    for (int i = 0; i < 4; i++) {
#pragma unroll
        for (int j = 0; j < 4; j++) {
            const int row0 = m0 + wm + 16 * i + r;
            const int col0 = n0 + wn + 8 * j + 2 * c;
            float2 bv = *(const float2*)&bias[col0];
            float2 lo = make_float2(d[i * 4 + j][0] + bv.x,
                                    d[i * 4 + j][1] + bv.y);
            float2 hi = make_float2(d[i * 4 + j][2] + bv.x,
                                    d[i * 4 + j][3] + bv.y);
            *(float2*)&C[(size_t)row0 * GN + col0]       = lo;
            *(float2*)&C[(size_t)(row0 + 8) * GN + col0] = hi;
        }
    }
}

// ---------------------------------------------------------------------------
// Compensated-tf32 flash attention (error-free splitting).
// Every operand x is split x = b + s with b = rna_tf32(x), s = x - b (exact);
// products of tf32 inputs are EXACT in the fp32 accumulator, so
// D = b*B + b*S + s*B carries ~2^-21 relative error (fp32-grade).
// CTA = 64 q-rows x head, 4 warps (16 rows each), 128 threads, KV tile 64.
// P never touches smem: S C-fragment -> PV A-fragment via __shfl_sync
// (row map identical; col remap = 2 source lanes + parity select).
// Strides: Q/K 68 (frag banks 4r+c), V 72 (frag banks 8c+r) - conflict-free.
// ---------------------------------------------------------------------------
#define AQST 68
#define AKST 68
#define AVST 72
#define SM_QB 0
#define SM_QS (SM_QB + 64 * AQST)      //  4352
#define SM_KB (SM_QS + 64 * AQST)      //  8704
#define SM_KS (SM_KB + 64 * AKST)      // 13056
#define SM_VB (SM_KS + 64 * AKST)      // 17408
#define SM_VS (SM_VB + 64 * AVST)      // 22016
#define ATTN_SMEM_FLOATS (SM_VS + 64 * AVST)   // 26624 floats = 106496 B

__device__ __forceinline__ void split4(float4 v, float4& b, float4& s) {
    uint32_t u;
    CVT_TF32(u, v.x); b.x = __uint_as_float(u); s.x = v.x - b.x;
    CVT_TF32(u, v.y); b.y = __uint_as_float(u); s.y = v.y - b.y;
    CVT_TF32(u, v.z); b.z = __uint_as_float(u); s.z = v.z - b.z;
    CVT_TF32(u, v.w); b.w = __uint_as_float(u); s.w = v.w - b.w;
}

__global__ void __launch_bounds__(128, 2) attn_kernel()
{
    extern __shared__ __align__(16) float sm[];
    float* Qb = sm + SM_QB;
    float* Qs = sm + SM_QS;
    float* Kb = sm + SM_KB;
    float* Ks = sm + SM_KS;
    float* Vb = sm + SM_VB;
    float* Vs = sm + SM_VS;

    const int h   = blockIdx.y;
    const int q0  = blockIdx.x * 64;
    const int tid = threadIdx.x;
    const int wid = tid >> 5;          // 0..3
    const int lid = tid & 31;
    const int r   = lid >> 2;          // 0..7
    const int c   = lid & 3;           // 0..3
    const int qrow = wid * 16;
    const int L1  = (lid & 28) | (c >> 1);   // shfl src for cols c / c+4
    const int L2  = L1 + 2;
    const bool codd = (c & 1);
    const float qscale = 0.125f * 1.44269504088896340736f;

    // ---- load Q tile (scaled), split big/small: 64x64, 8 float4/thread
#pragma unroll
    for (int t = 0; t < 8; t++) {
        int idx = tid + t * 128;
        int row = idx >> 4, c4 = (idx & 15) * 4;
        float4 v = *(const float4*)&g_Qp[(size_t)(q0 + row) * DIMV + h * HDIM + c4];
        v.x *= qscale; v.y *= qscale; v.z *= qscale; v.w *= qscale;
        float4 b, s;
        split4(v, b, s);
        *(float4*)&Qb[row * AQST + c4] = b;
        *(float4*)&Qs[row * AQST + c4] = s;
    }

    float o[8][4];
#pragma unroll
    for (int nt = 0; nt < 8; nt++)
#pragma unroll
        for (int j = 0; j < 4; j++) o[nt][j] = 0.f;
    float m_lo = -INFINITY, m_hi = -INFINITY, l_lo = 0.f, l_hi = 0.f;

    for (int j0 = 0; j0 < NKV; j0 += 64) {
        if (j0) __syncthreads();   // previous tile fully consumed
        // ---- fill K, V tiles split big/small (64x64 each)
#pragma unroll
        for (int t = 0; t < 8; t++) {
            int idx = tid + t * 128;
            int row = idx >> 4, c4 = (idx & 15) * 4;
            float4 kv4 = *(const float4*)&g_Kp[(size_t)(j0 + row) * DIMV + h * HDIM + c4];
            float4 b, s;
            split4(kv4, b, s);
            *(float4*)&Kb[row * AKST + c4] = b;
            *(float4*)&Ks[row * AKST + c4] = s;
            float4 vv4 = *(const float4*)&g_Vp[(size_t)(j0 + row) * DIMV + h * HDIM + c4];
            split4(vv4, b, s);
            *(float4*)&Vb[row * AVST + c4] = b;
            *(float4*)&Vs[row * AVST + c4] = s;
        }
        __syncthreads();   // tiles ready (also orders Q stores on iter 0)

        // ---- S = Q K^T, compensated (3 mma per tile pair)
        float s[8][4];
#pragma unroll
        for (int nt = 0; nt < 8; nt++)
#pragma unroll
            for (int j = 0; j < 4; j++) s[nt][j] = 0.f;

#pragma unroll
        for (int kt = 0; kt < 8; kt++) {
            const int kk = kt * 8;
            uint32_t ab[4], as[4];
            ab[0] = __float_as_uint(Qb[(qrow + r    ) * AQST + kk + c    ]);
            ab[1] = __float_as_uint(Qb[(qrow + r + 8) * AQST + kk + c    ]);
            ab[2] = __float_as_uint(Qb[(qrow + r    ) * AQST + kk + c + 4]);
            ab[3] = __float_as_uint(Qb[(qrow + r + 8) * AQST + kk + c + 4]);
            as[0] = __float_as_uint(Qs[(qrow + r    ) * AQST + kk + c    ]);
            as[1] = __float_as_uint(Qs[(qrow + r + 8) * AQST + kk + c    ]);
            as[2] = __float_as_uint(Qs[(qrow + r    ) * AQST + kk + c + 4]);
            as[3] = __float_as_uint(Qs[(qrow + r + 8) * AQST + kk + c + 4]);
#pragma unroll
            for (int nt = 0; nt < 8; nt++) {
                const int nr = nt * 8 + r;
                uint32_t bb[2], bs[2];
                bb[0] = __float_as_uint(Kb[nr * AKST + kk + c    ]);
                bb[1] = __float_as_uint(Kb[nr * AKST + kk + c + 4]);
                bs[0] = __float_as_uint(Ks[nr * AKST + kk + c    ]);
                bs[1] = __float_as_uint(Ks[nr * AKST + kk + c + 4]);
                mma_tf32(s[nt], ab, bb);
                mma_tf32(s[nt], ab, bs);
                mma_tf32(s[nt], as, bb);
            }
        }

        // ---- online softmax on fragment layout (rows r and r+8)
        float mx0 = m_lo, mx1 = m_hi;
#pragma unroll
        for (int nt = 0; nt < 8; nt++) {
            mx0 = fmaxf(mx0, fmaxf(s[nt][0], s[nt][1]));
            mx1 = fmaxf(mx1, fmaxf(s[nt][2], s[nt][3]));
        }
        mx0 = fmaxf(mx0, __shfl_xor_sync(0xffffffffu, mx0, 1));
        mx0 = fmaxf(mx0, __shfl_xor_sync(0xffffffffu, mx0, 2));
        mx1 = fmaxf(mx1, __shfl_xor_sync(0xffffffffu, mx1, 1));
        mx1 = fmaxf(mx1, __shfl_xor_sync(0xffffffffu, mx1, 2));

        float sum0 = 0.f, sum1 = 0.f;
#pragma unroll
        for (int nt = 0; nt < 8; nt++) {
            s[nt][0] = exp2f(s[nt][0] - mx0);
            s[nt][1] = exp2f(s[nt][1] - mx0);
            s[nt][2] = exp2f(s[nt][2] - mx1);
            s[nt][3] = exp2f(s[nt][3] - mx1);
            sum0 += s[nt][0] + s[nt][1];
            sum1 += s[nt][2] + s[nt][3];
        }
        sum0 += __shfl_xor_sync(0xffffffffu, sum0, 1);
        sum0 += __shfl_xor_sync(0xffffffffu, sum0, 2);
        sum1 += __shfl_xor_sync(0xffffffffu, sum1, 1);
        sum1 += __shfl_xor_sync(0xffffffffu, sum1, 2);

        const float corr0 = exp2f(m_lo - mx0);
        const float corr1 = exp2f(m_hi - mx1);
        m_lo = mx0; m_hi = mx1;
        l_lo = l_lo * corr0 + sum0;
        l_hi = l_hi * corr1 + sum1;
#pragma unroll
        for (int nt = 0; nt < 8; nt++) {
            o[nt][0] *= corr0; o[nt][1] *= corr0;
            o[nt][2] *= corr1; o[nt][3] *= corr1;
        }

        // ---- O += P V, compensated; P frags via shfl from S C-fragments
#pragma unroll
        for (int kt = 0; kt < 8; kt++) {
            const int kk = kt * 8;
            // A-frag remap: a0=P[r][kk+c] a1=P[r+8][kk+c] a2=P[r][kk+c+4] a3=P[r+8][kk+c+4]
            float e0 = __shfl_sync(0xffffffffu, s[kt][0], L1);
            float e1 = __shfl_sync(0xffffffffu, s[kt][1], L1);
            float e2 = __shfl_sync(0xffffffffu, s[kt][2], L1);
            float e3 = __shfl_sync(0xffffffffu, s[kt][3], L1);
            float f0 = __shfl_sync(0xffffffffu, s[kt][0], L2);
            float f1 = __shfl_sync(0xffffffffu, s[kt][1], L2);
            float f2 = __shfl_sync(0xffffffffu, s[kt][2], L2);
            float f3 = __shfl_sync(0xffffffffu, s[kt][3], L2);
            float a0 = codd ? e1 : e0;
            float a1 = codd ? e3 : e2;
            float a2 = codd ? f1 : f0;
            float a3 = codd ? f3 : f2;
            uint32_t pb[4], ps[4];
            float bb;
            CVT_TF32(pb[0], a0); bb = __uint_as_float(pb[0]); ps[0] = __float_as_uint(a0 - bb);
            CVT_TF32(pb[1], a1); bb = __uint_as_float(pb[1]); ps[1] = __float_as_uint(a1 - bb);
            CVT_TF32(pb[2], a2); bb = __uint_as_float(pb[2]); ps[2] = __float_as_uint(a2 - bb);
            CVT_TF32(pb[3], a3); bb = __uint_as_float(pb[3]); ps[3] = __float_as_uint(a3 - bb);
#pragma unroll
            for (int nt = 0; nt < 8; nt++) {
                uint32_t bvb[2], bvs[2];
                bvb[0] = __float_as_uint(Vb[(kk + c    ) * AVST + nt * 8 + r]);
                bvb[1] = __float_as_uint(Vb[(kk + c + 4) * AVST + nt * 8 + r]);
                bvs[0] = __float_as_uint(Vs[(kk + c    ) * AVST + nt * 8 + r]);
                bvs[1] = __float_as_uint(Vs[(kk + c + 4) * AVST + nt * 8 + r]);
                mma_tf32(o[nt], pb, bvb);
                mma_tf32(o[nt], pb, bvs);
                mma_tf32(o[nt], ps, bvb);
            }
        }
    }

    // ---- normalize and write O
    const float inv0 = 1.f / l_lo;
    const float inv1 = 1.f / l_hi;
    const int row_lo = q0 + qrow + r;
#pragma unroll
    for (int nt = 0; nt < 8; nt++) {
        const int col = h * HDIM + nt * 8 + 2 * c;
        *(float2*)&g_Ao[(size_t)row_lo * DIMV + col] =
            make_float2(o[nt][0] * inv0, o[nt][1] * inv0);
        *(float2*)&g_Ao[(size_t)(row_lo + 8) * DIMV + col] =
            make_float2(o[nt][2] * inv1, o[nt][3] * inv1);
    }
}

// ---------------------------------------------------------------------------
extern "C" void kernel_launch(void* const* d_in, const int* in_sizes, int n_in,
                              void* d_out, int out_size)
{
    const float* q   = (const float*)d_in[0];
    const float* kv  = (const float*)d_in[1];
    const float* q_w = (const float*)d_in[2];
    const float* q_b = (const float*)d_in[3];
    const float* k_w = (const float*)d_in[4];
    const float* k_b = (const float*)d_in[5];
    const float* v_w = (const float*)d_in[6];
    const float* v_b = (const float*)d_in[7];
    const float* o_w = (const float*)d_in[8];
    const float* o_b = (const float*)d_in[9];
    float* out = (float*)d_out;

    float *Qp, *Kp, *Vp, *Ao;
    cudaGetSymbolAddress((void**)&Qp, g_Qp);
    cudaGetSymbolAddress((void**)&Kp, g_Kp);
    cudaGetSymbolAddress((void**)&Vp, g_Vp);
    cudaGetSymbolAddress((void**)&Ao, g_Ao);

    const int attn_smem = ATTN_SMEM_FLOATS * (int)sizeof(float);  // 106496 B
    cudaFuncSetAttribute(attn_kernel,
                         cudaFuncAttributeMaxDynamicSharedMemorySize, attn_smem);

    dim3 gg(GN / 128, NQ / 128);   // (8, 32)

    gemm_tf32_kernel<<<gg, 256>>>(q,  q_w, q_b, Qp);
    gemm_tf32_kernel<<<gg, 256>>>(kv, k_w, k_b, Kp);
    gemm_tf32_kernel<<<gg, 256>>>(kv, v_w, v_b, Vp);

    attn_kernel<<<dim3(NQ / 64, NHEADS), 128, attn_smem>>>();

    gemm_tf32_kernel<<<gg, 256>>>(Ao, o_w, o_b, out);
}